// round 7
// baseline (speedup 1.0000x reference)
#include <cuda_runtime.h>
#include <cstddef>
#include <cstdint>

// DotMatrix on GB300 (sm_103a).
// out[b,i,j,t,c] = complex dot over m of A_i with SO3-conjugated A_j,
// concatenated over ell in {0..3} (M = 2*ell+1), tau = 32 per ell.
//
// Identity 1 (fold): flip+sign moves to the register-resident i-side.
// Identity 2 (symmetry): out[b,i,j,:] == out[b,j,i,:] -> upper-tri pairs only.
//
// R7 = R6 (cp.async ell-pipelined, 272 big blocks) with store-issue relief:
// tau-pair threads (16tp x 16ty), STG.128 outputs (halves store-issue cost),
// B tile transposed IN the cp.async copy to [(jl*M+m)*32+tau] so a tau-pair
// is one conflict-free broadcast LDS.128.

namespace cfg {
constexpr int kN = 256;
constexpr int kT = 32;                    // taus per ell
constexpr int JT = 16;                    // j-tile
constexpr int IT = 16;                    // i-tile (= TY, KI=1)
constexpr int TP = 16;                    // tau pairs
constexpr int TY = 16;
constexpr int NT = TP * TY;               // 256 threads
constexpr int NB = kN / JT;               // 16
constexpr int NPAIRS = NB * (NB + 1) / 2; // 136
// double buffer (float2 units): A holds ell 0/2 (max 2560 f2), B ell 1/3 (3584)
constexpr int OFF_A = 0;
constexpr int OFF_B = 2560;               // float2 units
constexpr int SHF2 = 2560 + 3584;         // 6144 float2 = 48KB
}
__device__ __forceinline__ constexpr int bufOff(int ell) {  // float2 units
  return (ell & 1) ? cfg::OFF_B : cfg::OFF_A;
}

__device__ __forceinline__ void cpAsync8(uint32_t s, const float2* g) {
  asm volatile("cp.async.ca.shared.global [%0], [%1], 8;\n" :: "r"(s), "l"(g));
}
template <int N>
__device__ __forceinline__ void cpWait() {
  asm volatile("cp.async.wait_group %0;\n" :: "n"(N));
}
__device__ __forceinline__ void cpCommit() {
  asm volatile("cp.async.commit_group;\n");
}

// Transposing async copy: global [(jl*32+tau)*M + m] -> smem [(jl*M+m)*32+tau]
template <int ELL>
__device__ __forceinline__ void copyAsync(const float* __restrict__ rep,
                                          uint32_t shAddr,
                                          int b, int j0, int tid) {
  using namespace cfg;
  constexpr int M = 2 * ELL + 1;
  constexpr int CNT2 = JT * kT * M;            // 512*M float2 elements
  const float2* src = reinterpret_cast<const float2*>(rep) +
                      (size_t)(b * kN + j0) * (kT * M);
  const uint32_t base = shAddr + bufOff(ELL) * 8;
#pragma unroll
  for (int k = 0; k < CNT2 / NT; ++k) {        // exactly 2*M iterations
    int idx = tid + k * NT;                    // coalesced global read
    int jt = idx / M;                          // constexpr M -> mul-hi
    int m = idx - jt * M;
    int tau = jt & 31;
    int jl = jt >> 5;
    uint32_t dst = base + (uint32_t)(((jl * M + m) << 5) + tau) * 8u;
    cpAsync8(dst, src + idx);
  }
  cpCommit();
}

template <int ELL>
__device__ __forceinline__ void doEll(const float* __restrict__ rep,
                                      const float* __restrict__ sh,
                                      int b, int i0, int j0,
                                      int tp, int ty, bool mirror,
                                      float4* __restrict__ out) {
  using namespace cfg;
  constexpr int M = 2 * ELL + 1;

  // A' (flip+sign folded) for taus {2tp, 2tp+1}, this thread's i-row.
  const int i = i0 + ty;
  float ar0[M], ai0[M], ar1[M], ai1[M];
  const float2* ab = reinterpret_cast<const float2*>(rep) +
                     (size_t)((b * kN + i) * kT + 2 * tp) * M;
#pragma unroll
  for (int m = 0; m < M; ++m) {
    float2 v0 = __ldg(&ab[M - 1 - m]);
    float2 v1 = __ldg(&ab[M + (M - 1 - m)]);
    float s = ((m + ELL) & 1) ? -1.0f : 1.0f;
    ar0[m] = s * v0.x; ai0[m] = s * v0.y;
    ar1[m] = s * v1.x; ai1[m] = s * v1.y;
  }
  // output bases in float4 units (out float4 = taus {2tp,2tp+1} x (re,im))
  unsigned ob = (unsigned)(((b * kN + i) * kN + j0) * 64 + ELL * TP + tp);
  unsigned om = (unsigned)(((b * kN + j0) * kN + i) * 64 + ELL * TP + tp);

  const float4* bb = reinterpret_cast<const float4*>(sh) +
                     (bufOff(ELL) >> 1) + tp;
#pragma unroll 4
  for (int jl = 0; jl < JT; ++jl) {
    float a10 = 0.f, a20 = 0.f, ci0 = 0.f;
    float a11 = 0.f, a21 = 0.f, ci1 = 0.f;
#pragma unroll
    for (int m = 0; m < M; ++m) {
      float4 bv = bb[(jl * M + m) * TP];   // LDS.128, bcast across ty-halves
      a10 = fmaf(ar0[m], bv.x, a10);
      a20 = fmaf(ai0[m], bv.y, a20);
      ci0 = fmaf(ar0[m], bv.y, ci0);
      ci0 = fmaf(ai0[m], bv.x, ci0);
      a11 = fmaf(ar1[m], bv.z, a11);
      a21 = fmaf(ai1[m], bv.w, a21);
      ci1 = fmaf(ar1[m], bv.w, ci1);
      ci1 = fmaf(ai1[m], bv.z, ci1);
    }
    float4 val = make_float4(a10 - a20, ci0, a11 - a21, ci1);
    __stcs(&out[ob + (unsigned)(jl * 64)], val);
    if (mirror)
      __stcs(&out[om + (unsigned)(jl * (kN * 64))], val);
  }
}

__global__ void __launch_bounds__(cfg::NT, 4)
dotmat_kernel(const float* __restrict__ r0, const float* __restrict__ r1,
              const float* __restrict__ r2, const float* __restrict__ r3,
              float4* __restrict__ out) {
  using namespace cfg;
  __shared__ float2 sh2[SHF2];
  const float* sh = reinterpret_cast<const float*>(sh2);
  const uint32_t shAddr = (uint32_t)__cvta_generic_to_shared(sh2);
  const int tp = threadIdx.x;
  const int ty = threadIdx.y;
  const int tid = ty * TP + tp;
  const int b  = blockIdx.y;

  // integer decode of upper-tri pair p -> (bi, bj), bi <= bj
  int p = blockIdx.x;
  int bi = 0;
  while (p >= NB - bi) { p -= NB - bi; ++bi; }
  const int bj = bi + p;

  const int i0 = bi * IT;
  const int j0 = bj * JT;
  const bool mirror = (bi != bj);

  // pipelined: copy(ell+1) in flight while compute(ell) runs
  copyAsync<0>(r0, shAddr, b, j0, tid);
  copyAsync<1>(r1, shAddr, b, j0, tid);
  cpWait<1>(); __syncthreads();                 // ell0 ready
  doEll<0>(r0, sh, b, i0, j0, tp, ty, mirror, out);
  __syncthreads();                              // done reading buf A
  copyAsync<2>(r2, shAddr, b, j0, tid);
  cpWait<1>(); __syncthreads();                 // ell1 ready
  doEll<1>(r1, sh, b, i0, j0, tp, ty, mirror, out);
  __syncthreads();                              // done reading buf B
  copyAsync<3>(r3, shAddr, b, j0, tid);
  cpWait<1>(); __syncthreads();                 // ell2 ready
  doEll<2>(r2, sh, b, i0, j0, tp, ty, mirror, out);
  cpWait<0>(); __syncthreads();                 // ell3 ready
  doEll<3>(r3, sh, b, i0, j0, tp, ty, mirror, out);
}

extern "C" void kernel_launch(void* const* d_in, const int* in_sizes, int n_in,
                              void* d_out, int out_size) {
  (void)in_sizes; (void)n_in; (void)out_size;
  dim3 grid(cfg::NPAIRS, 2);     // 136 tile pairs x 2 batches = 272 blocks
  dim3 block(cfg::TP, cfg::TY);  // 256 threads
  dotmat_kernel<<<grid, block>>>(
      (const float*)d_in[0], (const float*)d_in[1],
      (const float*)d_in[2], (const float*)d_in[3],
      (float4*)d_out);
}

// round 8
// speedup vs baseline: 1.0491x; 1.0491x over previous
#include <cuda_runtime.h>
#include <cstddef>
#include <cstdint>

// DotMatrix on GB300 (sm_103a).
// out[b,i,j,t,c] = complex dot over m of A_i with SO3-conjugated A_j,
// concatenated over ell in {0..3} (M = 2*ell+1), tau = 32 per ell.
//
// Identity 1 (fold): sum_m A_i[m]*sign(m)*A_j[M-1-m]
//                  == sum_m (sign(m)*A_i[M-1-m]) * A_j[m]
// Identity 2 (symmetry): out[b,i,j,:] == out[b,j,i,:] (both components)
//   -> upper-triangular tile pairs only; mirror-store off-diagonal tiles.
//
// R8 = R6 (best structure) with ALL FOUR ell tile copies committed upfront
// into disjoint smem regions (64KB dynamic smem): maximal copy MLP, zero
// mid-kernel copy issuance, no WAR buffer-reuse hazards. Stores stay
// full-lane STG.64 (optimal per-byte issue cost: 7.75 cyc / 256B / warp).

namespace cfg {
constexpr int kN = 256;
constexpr int kT = 32;                    // taus per ell
constexpr int JT = 16;                    // j-tile
constexpr int IT = 16;                    // i-tile = TY * KI
constexpr int KI = 2;
constexpr int TY = 8;
constexpr int NT = 32 * TY;               // 256 threads
constexpr int NB = kN / JT;               // 16
constexpr int NPAIRS = NB * (NB + 1) / 2; // 136
constexpr int SHF = 16384;                // 1024*sum(M) floats = 64KB dynamic
}
// smem float offset of ell tile (JT*kT*2M floats each): 1024 * ell^2
__device__ __forceinline__ constexpr int bufOff(int ell) {
  return 1024 * ell * ell;
}

__device__ __forceinline__ void cpAsync16(uint32_t s, const float4* g) {
  asm volatile("cp.async.cg.shared.global [%0], [%1], 16;\n" :: "r"(s), "l"(g));
}
template <int N>
__device__ __forceinline__ void cpWait() {
  asm volatile("cp.async.wait_group %0;\n" :: "n"(N));
}
__device__ __forceinline__ void cpCommit() {
  asm volatile("cp.async.commit_group;\n");
}

template <int ELL>
__device__ __forceinline__ void copyAsync(const float* __restrict__ rep,
                                          uint32_t shAddr,
                                          int b, int j0, int tid) {
  using namespace cfg;
  constexpr int M = 2 * ELL + 1;
  constexpr int CNT4 = JT * kT * M * 2 / 4;   // 256*M float4
  const float4* src = reinterpret_cast<const float4*>(
      rep + (size_t)(b * kN + j0) * (kT * M * 2));
  uint32_t dst = shAddr + bufOff(ELL) * 4 + tid * 16;
#pragma unroll
  for (int k = 0; k < CNT4 / NT; ++k)          // exactly M iterations
    cpAsync16(dst + k * (NT * 16), src + tid + k * NT);
  cpCommit();
}

template <int ELL>
__device__ __forceinline__ void doEll(const float* __restrict__ rep,
                                      const float* __restrict__ sh,
                                      int b, int i0, int j0,
                                      int tau, int ty, bool mirror,
                                      float2* __restrict__ out) {
  using namespace cfg;
  constexpr int M = 2 * ELL + 1;

  // A with flip+sign folded; KI i-rows, this thread's tau (L2-hot input).
  float ar[KI][M], ai[KI][M];
  unsigned ob[KI], om[KI];
#pragma unroll
  for (int ki = 0; ki < KI; ++ki) {
    const int i = i0 + ty + ki * TY;
    const float2* ab = reinterpret_cast<const float2*>(rep) +
                       (size_t)((b * kN + i) * kT + tau) * M;
#pragma unroll
    for (int m = 0; m < M; ++m) {
      float2 v = __ldg(&ab[M - 1 - m]);
      float s = ((m + ELL) & 1) ? -1.0f : 1.0f;
      ar[ki][m] = s * v.x;
      ai[ki][m] = s * v.y;
    }
    ob[ki] = (unsigned)(((b * kN + i) * kN + j0) * 128 + ELL * kT + tau);
    om[ki] = (unsigned)(((b * kN + j0) * kN + i) * 128 + ELL * kT + tau);
  }

  const float2* bbase =
      reinterpret_cast<const float2*>(sh + bufOff(ELL)) + tau * M;
#pragma unroll 4
  for (int jl = 0; jl < JT; ++jl) {
    const float2* bp = bbase + jl * (kT * M);
    float a1[KI], a2[KI], ci[KI];
#pragma unroll
    for (int ki = 0; ki < KI; ++ki) { a1[ki] = 0.f; a2[ki] = 0.f; ci[ki] = 0.f; }
#pragma unroll
    for (int m = 0; m < M; ++m) {
      float2 bv = bp[m];                  // conflict-free LDS.64
#pragma unroll
      for (int ki = 0; ki < KI; ++ki) {
        a1[ki] = fmaf(ar[ki][m], bv.x, a1[ki]);
        a2[ki] = fmaf(ai[ki][m], bv.y, a2[ki]);
        ci[ki] = fmaf(ar[ki][m], bv.y, ci[ki]);
        ci[ki] = fmaf(ai[ki][m], bv.x, ci[ki]);
      }
    }
#pragma unroll
    for (int ki = 0; ki < KI; ++ki) {
      float2 val = make_float2(a1[ki] - a2[ki], ci[ki]);
      __stcs(&out[ob[ki] + (unsigned)(jl * 128)], val);
      if (mirror)
        __stcs(&out[om[ki] + (unsigned)(jl * (kN * 128))], val);
    }
  }
}

__global__ void __launch_bounds__(cfg::NT, 3)
dotmat_kernel(const float* __restrict__ r0, const float* __restrict__ r1,
              const float* __restrict__ r2, const float* __restrict__ r3,
              float2* __restrict__ out) {
  using namespace cfg;
  extern __shared__ float sh[];
  const uint32_t shAddr = (uint32_t)__cvta_generic_to_shared(sh);
  const int tau = threadIdx.x;
  const int ty  = threadIdx.y;
  const int tid = ty * 32 + tau;
  const int b   = blockIdx.y;

  // integer decode of upper-tri pair p -> (bi, bj), bi <= bj
  int p = blockIdx.x;
  int bi = 0;
  while (p >= NB - bi) { p -= NB - bi; ++bi; }
  const int bj = bi + p;

  const int i0 = bi * IT;
  const int j0 = bj * JT;
  const bool mirror = (bi != bj);

  // all four copies in flight from t=0 (disjoint buffers, 4 groups)
  copyAsync<0>(r0, shAddr, b, j0, tid);
  copyAsync<1>(r1, shAddr, b, j0, tid);
  copyAsync<2>(r2, shAddr, b, j0, tid);
  copyAsync<3>(r3, shAddr, b, j0, tid);

  cpWait<3>(); __syncthreads();                 // ell0 ready
  doEll<0>(r0, sh, b, i0, j0, tau, ty, mirror, out);
  cpWait<2>(); __syncthreads();                 // ell1 ready
  doEll<1>(r1, sh, b, i0, j0, tau, ty, mirror, out);
  cpWait<1>(); __syncthreads();                 // ell2 ready
  doEll<2>(r2, sh, b, i0, j0, tau, ty, mirror, out);
  cpWait<0>(); __syncthreads();                 // ell3 ready
  doEll<3>(r3, sh, b, i0, j0, tau, ty, mirror, out);
}

extern "C" void kernel_launch(void* const* d_in, const int* in_sizes, int n_in,
                              void* d_out, int out_size) {
  (void)in_sizes; (void)n_in; (void)out_size;
  cudaFuncSetAttribute(dotmat_kernel,
                       cudaFuncAttributeMaxDynamicSharedMemorySize,
                       cfg::SHF * (int)sizeof(float));
  dim3 grid(cfg::NPAIRS, 2);     // 136 tile pairs x 2 batches = 272 blocks
  dim3 block(32, cfg::TY);       // 256 threads
  dotmat_kernel<<<grid, block, cfg::SHF * sizeof(float)>>>(
      (const float*)d_in[0], (const float*)d_in[1],
      (const float*)d_in[2], (const float*)d_in[3],
      (float2*)d_out);
}

// round 9
// speedup vs baseline: 1.0743x; 1.0240x over previous
#include <cuda_runtime.h>
#include <cstddef>
#include <cstdint>

// DotMatrix on GB300 (sm_103a).
// out[b,i,j,t,c] = complex dot over m of A_i with SO3-conjugated A_j,
// concatenated over ell in {0..3} (M = 2*ell+1), tau = 32 per ell.
//
// Identity 1 (fold): sum_m A_i[m]*sign(m)*A_j[M-1-m]
//                  == sum_m (sign(m)*A_i[M-1-m]) * A_j[m]
// Identity 2 (symmetry): out[b,i,j,:] == out[b,j,i,:] (both components)
//   -> upper-triangular tile pairs only; mirror-store off-diagonal tiles.
//
// R9 = R6 schedule + R8 structure + latency hoisting:
//  - 4 disjoint smem buffers (64KB dynamic): no WAR barriers (4 total).
//  - staggered cp.async commits (ell0-2 upfront, ell3 after ell0 compute):
//    avoids R8's 64KB read burst that collided with the previous launch's
//    L2->DRAM write drain in steady state.
//  - per-ell A-tile LDGs hoisted ABOVE the cp.async wait: global-latency
//    hidden behind the copy wait instead of exposed after each barrier.
//  - cheap (diagonal, mirror-free) blocks scheduled in the tail wave.

namespace cfg {
constexpr int kN = 256;
constexpr int kT = 32;                    // taus per ell
constexpr int JT = 16;                    // j-tile
constexpr int IT = 16;                    // i-tile = TY * KI
constexpr int KI = 2;
constexpr int TY = 8;
constexpr int NT = 32 * TY;               // 256 threads
constexpr int NB = kN / JT;               // 16
constexpr int NOFF = NB * (NB - 1) / 2;   // 120 strict-upper pairs
constexpr int NPAIRS = NOFF + NB;         // 136
constexpr int SHF = 16384;                // 64KB dynamic smem
}
// disjoint smem float offset per ell (tile = 1024*M floats): 1024*ell^2
__device__ __forceinline__ constexpr int bufOff(int ell) {
  return 1024 * ell * ell;
}

__device__ __forceinline__ void cpAsync16(uint32_t s, const float4* g) {
  asm volatile("cp.async.cg.shared.global [%0], [%1], 16;\n" :: "r"(s), "l"(g));
}
template <int N>
__device__ __forceinline__ void cpWait() {
  asm volatile("cp.async.wait_group %0;\n" :: "n"(N));
}
__device__ __forceinline__ void cpCommit() {
  asm volatile("cp.async.commit_group;\n");
}

template <int ELL>
__device__ __forceinline__ void copyAsync(const float* __restrict__ rep,
                                          uint32_t shAddr,
                                          int b, int j0, int tid) {
  using namespace cfg;
  constexpr int M = 2 * ELL + 1;
  constexpr int CNT4 = JT * kT * M * 2 / 4;   // 256*M float4
  const float4* src = reinterpret_cast<const float4*>(
      rep + (size_t)(b * kN + j0) * (kT * M * 2));
  uint32_t dst = shAddr + bufOff(ELL) * 4 + tid * 16;
#pragma unroll
  for (int k = 0; k < CNT4 / NT; ++k)          // exactly M iterations
    cpAsync16(dst + k * (NT * 16), src + tid + k * NT);
  cpCommit();
}

// ---- A-tile load (flip+sign folded), independent of smem: hoist above wait
template <int ELL>
__device__ __forceinline__ void loadA(const float* __restrict__ rep,
                                      int b, int i0, int tau, int ty,
                                      float (&ar)[cfg::KI][2 * ELL + 1],
                                      float (&ai)[cfg::KI][2 * ELL + 1]) {
  using namespace cfg;
  constexpr int M = 2 * ELL + 1;
#pragma unroll
  for (int ki = 0; ki < KI; ++ki) {
    const int i = i0 + ty + ki * TY;
    const float2* ab = reinterpret_cast<const float2*>(rep) +
                       (size_t)((b * kN + i) * kT + tau) * M;
#pragma unroll
    for (int m = 0; m < M; ++m) {
      float2 v = __ldg(&ab[M - 1 - m]);
      float s = ((m + ELL) & 1) ? -1.0f : 1.0f;
      ar[ki][m] = s * v.x;
      ai[ki][m] = s * v.y;
    }
  }
}

template <int ELL>
__device__ __forceinline__ void computeEll(const float* __restrict__ sh,
                                           const float (&ar)[cfg::KI][2 * ELL + 1],
                                           const float (&ai)[cfg::KI][2 * ELL + 1],
                                           int b, int i0, int j0,
                                           int tau, int ty, bool mirror,
                                           float2* __restrict__ out) {
  using namespace cfg;
  constexpr int M = 2 * ELL + 1;
  unsigned ob[KI], om[KI];
#pragma unroll
  for (int ki = 0; ki < KI; ++ki) {
    const int i = i0 + ty + ki * TY;
    ob[ki] = (unsigned)(((b * kN + i) * kN + j0) * 128 + ELL * kT + tau);
    om[ki] = (unsigned)(((b * kN + j0) * kN + i) * 128 + ELL * kT + tau);
  }
  const float2* bbase =
      reinterpret_cast<const float2*>(sh + bufOff(ELL)) + tau * M;
#pragma unroll 4
  for (int jl = 0; jl < JT; ++jl) {
    const float2* bp = bbase + jl * (kT * M);
    float a1[KI], a2[KI], ci[KI];
#pragma unroll
    for (int ki = 0; ki < KI; ++ki) { a1[ki] = 0.f; a2[ki] = 0.f; ci[ki] = 0.f; }
#pragma unroll
    for (int m = 0; m < M; ++m) {
      float2 bv = bp[m];                  // conflict-free LDS.64
#pragma unroll
      for (int ki = 0; ki < KI; ++ki) {
        a1[ki] = fmaf(ar[ki][m], bv.x, a1[ki]);
        a2[ki] = fmaf(ai[ki][m], bv.y, a2[ki]);
        ci[ki] = fmaf(ar[ki][m], bv.y, ci[ki]);
        ci[ki] = fmaf(ai[ki][m], bv.x, ci[ki]);
      }
    }
#pragma unroll
    for (int ki = 0; ki < KI; ++ki) {
      float2 val = make_float2(a1[ki] - a2[ki], ci[ki]);
      __stcs(&out[ob[ki] + (unsigned)(jl * 128)], val);
      if (mirror)
        __stcs(&out[om[ki] + (unsigned)(jl * (kN * 128))], val);
    }
  }
}

__global__ void __launch_bounds__(cfg::NT, 3)
dotmat_kernel(const float* __restrict__ r0, const float* __restrict__ r1,
              const float* __restrict__ r2, const float* __restrict__ r3,
              float2* __restrict__ out) {
  using namespace cfg;
  extern __shared__ float sh[];
  const uint32_t shAddr = (uint32_t)__cvta_generic_to_shared(sh);
  const int tau = threadIdx.x;
  const int ty  = threadIdx.y;
  const int tid = ty * 32 + tau;
  const int b   = blockIdx.y;

  // pair decode: p < NOFF -> strict-upper (bi < bj, mirror);
  // p >= NOFF -> diagonal (cheap, scheduled in the tail wave).
  int p = blockIdx.x;
  int bi, bj;
  if (p < NOFF) {
    bi = 0;
    while (p >= NB - 1 - bi) { p -= NB - 1 - bi; ++bi; }
    bj = bi + 1 + p;
  } else {
    bi = bj = p - NOFF;
  }
  const int i0 = bi * IT;
  const int j0 = bj * JT;
  const bool mirror = (bi != bj);

  // staggered copy commits into disjoint buffers
  copyAsync<0>(r0, shAddr, b, j0, tid);
  copyAsync<1>(r1, shAddr, b, j0, tid);
  copyAsync<2>(r2, shAddr, b, j0, tid);

  {
    float ar[KI][1], ai[KI][1];
    loadA<0>(r0, b, i0, tau, ty, ar, ai);       // hoisted above wait
    cpWait<2>(); __syncthreads();               // ell0 ready
    computeEll<0>(sh, ar, ai, b, i0, j0, tau, ty, mirror, out);
  }
  copyAsync<3>(r3, shAddr, b, j0, tid);         // disjoint buf: no barrier
  {
    float ar[KI][3], ai[KI][3];
    loadA<1>(r1, b, i0, tau, ty, ar, ai);
    cpWait<2>(); __syncthreads();               // ell1 ready
    computeEll<1>(sh, ar, ai, b, i0, j0, tau, ty, mirror, out);
  }
  {
    float ar[KI][5], ai[KI][5];
    loadA<2>(r2, b, i0, tau, ty, ar, ai);
    cpWait<1>(); __syncthreads();               // ell2 ready
    computeEll<2>(sh, ar, ai, b, i0, j0, tau, ty, mirror, out);
  }
  {
    float ar[KI][7], ai[KI][7];
    loadA<3>(r3, b, i0, tau, ty, ar, ai);
    cpWait<0>(); __syncthreads();               // ell3 ready
    computeEll<3>(sh, ar, ai, b, i0, j0, tau, ty, mirror, out);
  }
}

extern "C" void kernel_launch(void* const* d_in, const int* in_sizes, int n_in,
                              void* d_out, int out_size) {
  (void)in_sizes; (void)n_in; (void)out_size;
  cudaFuncSetAttribute(dotmat_kernel,
                       cudaFuncAttributeMaxDynamicSharedMemorySize,
                       cfg::SHF * (int)sizeof(float));
  dim3 grid(cfg::NPAIRS, 2);     // 136 tile pairs x 2 batches = 272 blocks
  dim3 block(32, cfg::TY);       // 256 threads
  dotmat_kernel<<<grid, block, cfg::SHF * sizeof(float)>>>(
      (const float*)d_in[0], (const float*)d_in[1],
      (const float*)d_in[2], (const float*)d_in[3],
      (float2*)d_out);
}

// round 10
// speedup vs baseline: 1.0820x; 1.0072x over previous
#include <cuda_runtime.h>
#include <cstddef>
#include <cstdint>

// DotMatrix on GB300 (sm_103a).
// out[b,i,j,t,c] = complex dot over m of A_i with SO3-conjugated A_j,
// concatenated over ell in {0..3} (M = 2*ell+1), tau = 32 per ell.
//
// Identity 1 (fold): sum_m A_i[m]*sign(m)*A_j[M-1-m]
//                  == sum_m (sign(m)*A_i[M-1-m]) * A_j[m]
// Identity 2 (symmetry): out[b,i,j,:] == out[b,j,i,:] (both components)
//   -> upper-triangular tile pairs only; mirror-store off-diagonal tiles.
//
// R10: 48KB STATIC smem (the empirically fast config: every 64KB-dynamic
// variant regressed steady-state timing) with an overlapping layout:
//   tile2 [0,5120) | tile0 [5120,6144) | tile1 [6144,9216) | tile3 [5120,12288)
// tile3 exactly overlays tiles 0+1 (+slack), so copies 0/1/2 commit upfront,
// copy3 commits after ell0+ell1 are consumed. 4 barriers total. A-tile LDGs
// hoisted above the cp.async waits. Diagonal (cheap) blocks in the tail wave.

namespace cfg {
constexpr int kN = 256;
constexpr int kT = 32;                    // taus per ell
constexpr int JT = 16;                    // j-tile
constexpr int IT = 16;                    // i-tile = TY * KI
constexpr int KI = 2;
constexpr int TY = 8;
constexpr int NT = 32 * TY;               // 256 threads
constexpr int NB = kN / JT;               // 16
constexpr int NOFF = NB * (NB - 1) / 2;   // 120 strict-upper pairs
constexpr int NPAIRS = NOFF + NB;         // 136
constexpr int SHF = 12288;                // 48KB static
}
// overlapping smem layout (floats): ell2 at 0; ell0 at 5120; ell1 at 6144;
// ell3 at 5120 (overlays 0+1, written only after both are consumed).
__device__ __forceinline__ constexpr int bufOff(int ell) {
  return ell == 2 ? 0 : (ell == 1 ? 6144 : 5120);
}

__device__ __forceinline__ void cpAsync16(uint32_t s, const float4* g) {
  asm volatile("cp.async.cg.shared.global [%0], [%1], 16;\n" :: "r"(s), "l"(g));
}
template <int N>
__device__ __forceinline__ void cpWait() {
  asm volatile("cp.async.wait_group %0;\n" :: "n"(N));
}
__device__ __forceinline__ void cpCommit() {
  asm volatile("cp.async.commit_group;\n");
}

template <int ELL>
__device__ __forceinline__ void copyAsync(const float* __restrict__ rep,
                                          uint32_t shAddr,
                                          int b, int j0, int tid) {
  using namespace cfg;
  constexpr int M = 2 * ELL + 1;
  constexpr int CNT4 = JT * kT * M * 2 / 4;   // 256*M float4
  const float4* src = reinterpret_cast<const float4*>(
      rep + (size_t)(b * kN + j0) * (kT * M * 2));
  uint32_t dst = shAddr + bufOff(ELL) * 4 + tid * 16;
#pragma unroll
  for (int k = 0; k < CNT4 / NT; ++k)          // exactly M iterations
    cpAsync16(dst + k * (NT * 16), src + tid + k * NT);
  cpCommit();
}

// A-tile load (flip+sign folded); independent of smem -> hoist above waits.
template <int ELL>
__device__ __forceinline__ void loadA(const float* __restrict__ rep,
                                      int b, int i0, int tau, int ty,
                                      float (&ar)[cfg::KI][2 * ELL + 1],
                                      float (&ai)[cfg::KI][2 * ELL + 1]) {
  using namespace cfg;
  constexpr int M = 2 * ELL + 1;
#pragma unroll
  for (int ki = 0; ki < KI; ++ki) {
    const int i = i0 + ty + ki * TY;
    const float2* ab = reinterpret_cast<const float2*>(rep) +
                       (size_t)((b * kN + i) * kT + tau) * M;
#pragma unroll
    for (int m = 0; m < M; ++m) {
      float2 v = __ldg(&ab[M - 1 - m]);
      float s = ((m + ELL) & 1) ? -1.0f : 1.0f;
      ar[ki][m] = s * v.x;
      ai[ki][m] = s * v.y;
    }
  }
}

template <int ELL>
__device__ __forceinline__ void computeEll(const float* __restrict__ sh,
                                           const float (&ar)[cfg::KI][2 * ELL + 1],
                                           const float (&ai)[cfg::KI][2 * ELL + 1],
                                           int b, int i0, int j0,
                                           int tau, int ty, bool mirror,
                                           float2* __restrict__ out) {
  using namespace cfg;
  constexpr int M = 2 * ELL + 1;
  unsigned ob[KI], om[KI];
#pragma unroll
  for (int ki = 0; ki < KI; ++ki) {
    const int i = i0 + ty + ki * TY;
    ob[ki] = (unsigned)(((b * kN + i) * kN + j0) * 128 + ELL * kT + tau);
    om[ki] = (unsigned)(((b * kN + j0) * kN + i) * 128 + ELL * kT + tau);
  }
  const float2* bbase =
      reinterpret_cast<const float2*>(sh + bufOff(ELL)) + tau * M;
#pragma unroll 4
  for (int jl = 0; jl < JT; ++jl) {
    const float2* bp = bbase + jl * (kT * M);
    float a1[KI], a2[KI], ci[KI];
#pragma unroll
    for (int ki = 0; ki < KI; ++ki) { a1[ki] = 0.f; a2[ki] = 0.f; ci[ki] = 0.f; }
#pragma unroll
    for (int m = 0; m < M; ++m) {
      float2 bv = bp[m];                  // conflict-free LDS.64
#pragma unroll
      for (int ki = 0; ki < KI; ++ki) {
        a1[ki] = fmaf(ar[ki][m], bv.x, a1[ki]);
        a2[ki] = fmaf(ai[ki][m], bv.y, a2[ki]);
        ci[ki] = fmaf(ar[ki][m], bv.y, ci[ki]);
        ci[ki] = fmaf(ai[ki][m], bv.x, ci[ki]);
      }
    }
#pragma unroll
    for (int ki = 0; ki < KI; ++ki) {
      float2 val = make_float2(a1[ki] - a2[ki], ci[ki]);
      __stcs(&out[ob[ki] + (unsigned)(jl * 128)], val);
      if (mirror)
        __stcs(&out[om[ki] + (unsigned)(jl * (kN * 128))], val);
    }
  }
}

__global__ void __launch_bounds__(cfg::NT, 3)
dotmat_kernel(const float* __restrict__ r0, const float* __restrict__ r1,
              const float* __restrict__ r2, const float* __restrict__ r3,
              float2* __restrict__ out) {
  using namespace cfg;
  __shared__ float sh[SHF];
  const uint32_t shAddr = (uint32_t)__cvta_generic_to_shared(sh);
  const int tau = threadIdx.x;
  const int ty  = threadIdx.y;
  const int tid = ty * 32 + tau;
  const int b   = blockIdx.y;

  // pair decode: strict-upper pairs first, diagonal (cheap) in the tail.
  int p = blockIdx.x;
  int bi, bj;
  if (p < NOFF) {
    bi = 0;
    while (p >= NB - 1 - bi) { p -= NB - 1 - bi; ++bi; }
    bj = bi + 1 + p;
  } else {
    bi = bj = p - NOFF;
  }
  const int i0 = bi * IT;
  const int j0 = bj * JT;
  const bool mirror = (bi != bj);

  // copies 0/1/2 upfront into disjoint regions
  copyAsync<0>(r0, shAddr, b, j0, tid);
  copyAsync<1>(r1, shAddr, b, j0, tid);
  copyAsync<2>(r2, shAddr, b, j0, tid);

  {
    float ar0[KI][1], ai0[KI][1];
    float ar1[KI][3], ai1[KI][3];
    loadA<0>(r0, b, i0, tau, ty, ar0, ai0);     // hoisted above wait
    loadA<1>(r1, b, i0, tau, ty, ar1, ai1);
    cpWait<1>(); __syncthreads();               // ell0 + ell1 ready
    computeEll<0>(sh, ar0, ai0, b, i0, j0, tau, ty, mirror, out);
    computeEll<1>(sh, ar1, ai1, b, i0, j0, tau, ty, mirror, out);
  }
  __syncthreads();                              // WAR: tiles 0+1 consumed
  copyAsync<3>(r3, shAddr, b, j0, tid);         // overlays tiles 0+1
  {
    float ar[KI][5], ai[KI][5];
    loadA<2>(r2, b, i0, tau, ty, ar, ai);
    float ar3[KI][7], ai3[KI][7];
    loadA<3>(r3, b, i0, tau, ty, ar3, ai3);     // overlaps compute2
    cpWait<1>(); __syncthreads();               // ell2 ready
    computeEll<2>(sh, ar, ai, b, i0, j0, tau, ty, mirror, out);
    cpWait<0>(); __syncthreads();               // ell3 ready
    computeEll<3>(sh, ar3, ai3, b, i0, j0, tau, ty, mirror, out);
  }
}

extern "C" void kernel_launch(void* const* d_in, const int* in_sizes, int n_in,
                              void* d_out, int out_size) {
  (void)in_sizes; (void)n_in; (void)out_size;
  dim3 grid(cfg::NPAIRS, 2);     // 136 tile pairs x 2 batches = 272 blocks
  dim3 block(32, cfg::TY);       // 256 threads
  dotmat_kernel<<<grid, block>>>(
      (const float*)d_in[0], (const float*)d_in[1],
      (const float*)d_in[2], (const float*)d_in[3],
      (float2*)d_out);
}